// round 3
// baseline (speedup 1.0000x reference)
#include <cuda_runtime.h>

#define FEAT   40
#define EDIM   64
#define ADIM   64
#define NPAIR  780          // FEAT*(FEAT-1)/2
#define NT     256
#define TILE_P 128
#define NTILES 7            // ceil(780/128)

typedef unsigned long long u64;

// ---------------------------------------------------------------------------
// Packed f32x2 helpers (sm_100a+). ptxas never auto-fuses these.
// ---------------------------------------------------------------------------
__device__ __forceinline__ u64 fma2(u64 a, u64 b, u64 c) {
    u64 d;
    asm("fma.rn.f32x2 %0, %1, %2, %3;" : "=l"(d) : "l"(a), "l"(b), "l"(c));
    return d;
}
__device__ __forceinline__ u64 pack2(float v) {
    u64 d;
    unsigned u = __float_as_uint(v);
    asm("mov.b64 %0, {%1, %1};" : "=l"(d) : "r"(u));
    return d;
}
__device__ __forceinline__ float lo32(u64 v) { return __uint_as_float((unsigned)v); }
__device__ __forceinline__ float hi32(u64 v) { return __uint_as_float((unsigned)(v >> 32)); }

struct __align__(16) Smem {
    u64   Wd[EDIM * ADIM];        // 32768  W duplicated: Wd[e][a] = (w,w)
    u64   bsd[ADIM];              // 512    bias duplicated
    float xs[FEAT * EDIM];        // 10240  staged x row-block
    float BIt[EDIM * TILE_P];     // 32768  BI tile, transposed [e][p_local]
    float sc[NPAIR];              // 3120   scores -> exp weights
    float scpart[TILE_P * 17];    // 8704   per-(pair, a-group) partials (pad 17)
    float partial[4 * EDIM];      // 1024
    float hs[ADIM];
    float pws[EDIM];
    float red[8];
    unsigned char pii[NPAIR];
    unsigned char pjj[NPAIR];
};

__global__ __launch_bounds__(NT, 2)
void afm_main_kernel(const float* __restrict__ x,
                     const float* __restrict__ W,
                     const float* __restrict__ bias,
                     const float* __restrict__ h,
                     const float* __restrict__ pw,
                     float* __restrict__ out) {
    extern __shared__ char smem_raw[];
    Smem* s = reinterpret_cast<Smem*>(smem_raw);

    const int b   = blockIdx.x;
    const int tid = threadIdx.x;

    // ---------------- Phase 0: stage inputs ----------------
    {
        const float4* xb4 = (const float4*)(x + (long)b * FEAT * EDIM);
        float4* xs4 = (float4*)s->xs;
        #pragma unroll
        for (int i = tid; i < FEAT * EDIM / 4; i += NT) xs4[i] = xb4[i];
        // W duplicated into 64-bit lanes (broadcast-friendly)
        for (int i = tid; i < EDIM * ADIM; i += NT) s->Wd[i] = pack2(W[i]);
        if (tid < ADIM) { s->bsd[tid] = pack2(bias[tid]); s->hs[tid] = h[tid]; }
        if (tid < EDIM) s->pws[tid] = pw[tid];
        if (tid < FEAT - 1) {
            int i = tid;
            int base = i * (FEAT - 1) - i * (i - 1) / 2;
            for (int j = i + 1; j < FEAT; j++) {
                s->pii[base + j - i - 1] = (unsigned char)i;
                s->pjj[base + j - i - 1] = (unsigned char)j;
            }
        }
    }
    __syncthreads();

    const int pg = tid & 15;        // pair-group: pairs 8*pg .. 8*pg+7
    const int ag = tid >> 4;        // a-group: cols 4*ag .. 4*ag+3
    const int a0 = 4 * ag;

    // bias init values for this thread's 4 a-columns (hoisted out of tile loop)
    const ulonglong2* bsp = (const ulonglong2*)(s->bsd + a0);
    const ulonglong2 bini0 = bsp[0];
    const ulonglong2 bini1 = bsp[1];

    // ---------------- Phase 1: tiled GEMM + fused ReLU/h epilogue ----------
    for (int tile = 0; tile < NTILES; tile++) {
        // --- build transposed BI tile: BIt[e][pl] = xs[i][e]*xs[j][e] ---
        {
            const int pl   = tid & 127;
            const int half = tid >> 7;      // e-half
            const int p    = tile * TILE_P + pl;
            if (p < NPAIR) {
                const int i = s->pii[p];
                const int j = s->pjj[p];
                const float4* xi = (const float4*)(s->xs + i * EDIM);
                const float4* xj = (const float4*)(s->xs + j * EDIM);
                #pragma unroll
                for (int e4 = half * 8; e4 < half * 8 + 8; e4++) {
                    float4 a = xi[e4];
                    float4 c = xj[e4];
                    int e0 = e4 * 4;
                    s->BIt[(e0 + 0) * TILE_P + pl] = a.x * c.x;
                    s->BIt[(e0 + 1) * TILE_P + pl] = a.y * c.y;
                    s->BIt[(e0 + 2) * TILE_P + pl] = a.z * c.z;
                    s->BIt[(e0 + 3) * TILE_P + pl] = a.w * c.w;
                }
            } else {
                #pragma unroll
                for (int e4 = half * 8; e4 < half * 8 + 8; e4++) {
                    int e0 = e4 * 4;
                    s->BIt[(e0 + 0) * TILE_P + pl] = 0.f;
                    s->BIt[(e0 + 1) * TILE_P + pl] = 0.f;
                    s->BIt[(e0 + 2) * TILE_P + pl] = 0.f;
                    s->BIt[(e0 + 3) * TILE_P + pl] = 0.f;
                }
            }
        }
        __syncthreads();

        // --- register-tiled GEMM: 8 pairs x 4 a per thread ---
        // acc[pp][aa] packs (pair 2pp, pair 2pp+1) for column a0+aa.
        // Bias folded into the init.
        u64 acc[4][4];
        #pragma unroll
        for (int pp = 0; pp < 4; pp++) {
            acc[pp][0] = bini0.x;
            acc[pp][1] = bini0.y;
            acc[pp][2] = bini1.x;
            acc[pp][3] = bini1.y;
        }

        #pragma unroll 4
        for (int e = 0; e < EDIM; e++) {
            const ulonglong2* bp = (const ulonglong2*)(s->BIt + e * TILE_P + 8 * pg);
            ulonglong2 bA = bp[0];          // pairs (0,1),(2,3)
            ulonglong2 bB = bp[1];          // pairs (4,5),(6,7)
            const ulonglong2* wp = (const ulonglong2*)(s->Wd + e * ADIM + a0);
            ulonglong2 wA = wp[0];          // dup w[a0], dup w[a0+1]
            ulonglong2 wB = wp[1];          // dup w[a0+2], dup w[a0+3]
            acc[0][0] = fma2(bA.x, wA.x, acc[0][0]);
            acc[0][1] = fma2(bA.x, wA.y, acc[0][1]);
            acc[0][2] = fma2(bA.x, wB.x, acc[0][2]);
            acc[0][3] = fma2(bA.x, wB.y, acc[0][3]);
            acc[1][0] = fma2(bA.y, wA.x, acc[1][0]);
            acc[1][1] = fma2(bA.y, wA.y, acc[1][1]);
            acc[1][2] = fma2(bA.y, wB.x, acc[1][2]);
            acc[1][3] = fma2(bA.y, wB.y, acc[1][3]);
            acc[2][0] = fma2(bB.x, wA.x, acc[2][0]);
            acc[2][1] = fma2(bB.x, wA.y, acc[2][1]);
            acc[2][2] = fma2(bB.x, wB.x, acc[2][2]);
            acc[2][3] = fma2(bB.x, wB.y, acc[2][3]);
            acc[3][0] = fma2(bB.y, wA.x, acc[3][0]);
            acc[3][1] = fma2(bB.y, wA.y, acc[3][1]);
            acc[3][2] = fma2(bB.y, wB.x, acc[3][2]);
            acc[3][3] = fma2(bB.y, wB.y, acc[3][3]);
        }

        // --- fused epilogue: relu(z) . h over this thread's 4 a's ---
        #pragma unroll
        for (int pp = 0; pp < 4; pp++) {
            float s0 = 0.f, s1 = 0.f;
            #pragma unroll
            for (int aa = 0; aa < 4; aa++) {
                float hv = s->hs[a0 + aa];
                s0 = fmaf(fmaxf(lo32(acc[pp][aa]), 0.f), hv, s0);
                s1 = fmaf(fmaxf(hi32(acc[pp][aa]), 0.f), hv, s1);
            }
            s->scpart[(8 * pg + 2 * pp)     * 17 + ag] = s0;
            s->scpart[(8 * pg + 2 * pp + 1) * 17 + ag] = s1;
        }
        __syncthreads();

        // --- reduce 16 a-group partials into the score ---
        if (tid < TILE_P) {
            int p = tile * TILE_P + tid;
            if (p < NPAIR) {
                float t0 = 0.f;
                #pragma unroll
                for (int g = 0; g < 16; g++) t0 += s->scpart[tid * 17 + g];
                s->sc[p] = t0;
            }
        }
        __syncthreads();
    }

    // ---------------- Phase 2: softmax over 780 scores ----------------
    float m = -3.402823466e38f;
    for (int p = tid; p < NPAIR; p += NT) m = fmaxf(m, s->sc[p]);
    #pragma unroll
    for (int o = 16; o; o >>= 1) m = fmaxf(m, __shfl_xor_sync(0xffffffffu, m, o));
    if ((tid & 31) == 0) s->red[tid >> 5] = m;
    __syncthreads();
    if (tid == 0) {
        float mm = s->red[0];
        #pragma unroll
        for (int w = 1; w < 8; w++) mm = fmaxf(mm, s->red[w]);
        s->red[0] = mm;
    }
    __syncthreads();
    m = s->red[0];
    __syncthreads();

    float sum = 0.f;
    for (int p = tid; p < NPAIR; p += NT) {
        float e0 = __expf(s->sc[p] - m);
        s->sc[p] = e0;
        sum += e0;
    }
    #pragma unroll
    for (int o = 16; o; o >>= 1) sum += __shfl_xor_sync(0xffffffffu, sum, o);
    if ((tid & 31) == 0) s->red[tid >> 5] = sum;
    __syncthreads();
    if (tid == 0) {
        float ss = s->red[0];
        #pragma unroll
        for (int w = 1; w < 8; w++) ss += s->red[w];
        s->red[0] = ss;
    }
    __syncthreads();
    const float scale = (float)NPAIR / s->red[0];

    // ---------------- Phase 3: weighted pooling + final dot ----------------
    {
        const int e = tid & 63;
        const int g = tid >> 6;
        float acc = 0.f;
        for (int p = g; p < NPAIR; p += 4) {
            float w = s->sc[p];
            int   i = s->pii[p];
            int   j = s->pjj[p];
            acc = fmaf(w, s->xs[i * EDIM + e] * s->xs[j * EDIM + e], acc);
        }
        s->partial[g * EDIM + e] = acc;
    }
    __syncthreads();
    if (tid < EDIM) {
        float pooled = (s->partial[tid] + s->partial[EDIM + tid]) +
                       (s->partial[2 * EDIM + tid] + s->partial[3 * EDIM + tid]);
        s->partial[tid] = pooled * scale * s->pws[tid];
    }
    __syncthreads();
    if (tid < 32) {
        float v = s->partial[tid] + s->partial[tid + 32];
        #pragma unroll
        for (int o = 16; o; o >>= 1) v += __shfl_xor_sync(0xffffffffu, v, o);
        if (tid == 0) out[b] = v;
    }
}

extern "C" void kernel_launch(void* const* d_in, const int* in_sizes, int n_in,
                              void* d_out, int out_size) {
    const float* x    = (const float*)d_in[0];
    const float* W    = (const float*)d_in[1];
    const float* bias = (const float*)d_in[2];
    const float* h    = (const float*)d_in[3];
    const float* pw   = (const float*)d_in[4];
    float* out = (float*)d_out;

    int B = in_sizes[0] / (FEAT * EDIM);
    size_t smem_bytes = sizeof(Smem);

    static bool attr_set = false;
    if (!attr_set) {
        cudaFuncSetAttribute(afm_main_kernel,
                             cudaFuncAttributeMaxDynamicSharedMemorySize,
                             (int)smem_bytes);
        attr_set = true;
    }

    afm_main_kernel<<<B, NT, smem_bytes>>>(x, W, bias, h, pw, out);
}

// round 4
// speedup vs baseline: 1.5729x; 1.5729x over previous
#include <cuda_runtime.h>

#define FEAT   40
#define EDIM   64
#define ADIM   64
#define NPAIR  780          // FEAT*(FEAT-1)/2
#define NT     256
#define TILE_P 128
#define NTILES 7            // ceil(780/128)

typedef unsigned long long u64;

// ---------------------------------------------------------------------------
// Packed f32x2 helpers (sm_100a+). ptxas never auto-fuses these.
// ---------------------------------------------------------------------------
__device__ __forceinline__ u64 fma2(u64 a, u64 b, u64 c) {
    u64 d;
    asm("fma.rn.f32x2 %0, %1, %2, %3;" : "=l"(d) : "l"(a), "l"(b), "l"(c));
    return d;
}
__device__ __forceinline__ u64 pack2(float v) {
    u64 d;
    unsigned u = __float_as_uint(v);
    asm("mov.b64 %0, {%1, %1};" : "=l"(d) : "r"(u));
    return d;
}
__device__ __forceinline__ float lo32(u64 v) { return __uint_as_float((unsigned)v); }
__device__ __forceinline__ float hi32(u64 v) { return __uint_as_float((unsigned)(v >> 32)); }

struct __align__(16) Smem {
    float Ws[EDIM * ADIM];        // 16384  W native [e][a]; (w_a,w_a+1) packs free
    float xs[FEAT * EDIM];        // 10240
    float BIt[EDIM * TILE_P];     // 32768  BI tile transposed [e][p_local]
    float sc[NPAIR];              // 3120
    float scpart[TILE_P * 2];     // 1024   per-(pair, a-block) partials
    float partial[4 * EDIM];      // 1024
    float bs[ADIM];
    float hs[ADIM];
    float pws[EDIM];
    float red[8];
    unsigned char pii[NPAIR];
    unsigned char pjj[NPAIR];
};

__global__ __launch_bounds__(NT, 3)
void afm_main_kernel(const float* __restrict__ x,
                     const float* __restrict__ W,
                     const float* __restrict__ bias,
                     const float* __restrict__ h,
                     const float* __restrict__ pw,
                     float* __restrict__ out) {
    extern __shared__ char smem_raw[];
    Smem* s = reinterpret_cast<Smem*>(smem_raw);

    const int b   = blockIdx.x;
    const int tid = threadIdx.x;

    // ---------------- Phase 0: stage inputs ----------------
    {
        const float4* xb4 = (const float4*)(x + (long)b * FEAT * EDIM);
        float4* xs4 = (float4*)s->xs;
        for (int i = tid; i < FEAT * EDIM / 4; i += NT) xs4[i] = xb4[i];
        const float4* w4 = (const float4*)W;
        float4* ws4 = (float4*)s->Ws;
        for (int i = tid; i < EDIM * ADIM / 4; i += NT) ws4[i] = w4[i];
        if (tid < ADIM) { s->bs[tid] = bias[tid]; s->hs[tid] = h[tid]; }
        if (tid < EDIM) s->pws[tid] = pw[tid];
        if (tid < FEAT - 1) {
            int i = tid;
            int base = i * (FEAT - 1) - i * (i - 1) / 2;
            for (int j = i + 1; j < FEAT; j++) {
                s->pii[base + j - i - 1] = (unsigned char)i;
                s->pjj[base + j - i - 1] = (unsigned char)j;
            }
        }
    }
    __syncthreads();

    // Warp-internal layout: both pair- and a-dim inside the warp so that
    // BIt and W LDS.128 each span exactly 128B per warp (1 wavefront).
    const int lid  = tid & 31;
    const int wid  = tid >> 5;          // 8 warps
    const int pg_w = lid & 7;           // 8 pair-groups within warp
    const int ag_w = lid >> 3;          // 4 a-groups within warp
    const int pblk = wid & 3;           // 4 pair-blocks of 32 -> 128 pairs
    const int ablk = wid >> 2;          // 2 a-blocks of 32 -> 64 a
    const int p_off = pblk * 32 + 4 * pg_w;   // first of this thread's 4 pairs
    const int a0    = ablk * 32 + 8 * ag_w;   // first of this thread's 8 a-cols

    // bias (packed pairs) for this thread's 8 a-columns
    const ulonglong2* bsp = (const ulonglong2*)(s->bs + a0);
    const ulonglong2 bini0 = bsp[0];
    const ulonglong2 bini1 = bsp[1];

    // ---------------- Phase 1: tiled GEMM + fused ReLU/h epilogue ----------
    for (int tile = 0; tile < NTILES; tile++) {
        // --- build transposed BI tile: BIt[e][pl] = xs[i][e]*xs[j][e] ---
        {
            const int pl   = tid & 127;
            const int half = tid >> 7;
            const int p    = tile * TILE_P + pl;
            if (p < NPAIR) {
                const int i = s->pii[p];
                const int j = s->pjj[p];
                const float4* xi = (const float4*)(s->xs + i * EDIM);
                const float4* xj = (const float4*)(s->xs + j * EDIM);
                #pragma unroll
                for (int e4 = half * 8; e4 < half * 8 + 8; e4++) {
                    float4 a = xi[e4];
                    float4 c = xj[e4];
                    int e0 = e4 * 4;
                    s->BIt[(e0 + 0) * TILE_P + pl] = a.x * c.x;
                    s->BIt[(e0 + 1) * TILE_P + pl] = a.y * c.y;
                    s->BIt[(e0 + 2) * TILE_P + pl] = a.z * c.z;
                    s->BIt[(e0 + 3) * TILE_P + pl] = a.w * c.w;
                }
            } else {
                #pragma unroll
                for (int e4 = half * 8; e4 < half * 8 + 8; e4++) {
                    int e0 = e4 * 4;
                    s->BIt[(e0 + 0) * TILE_P + pl] = 0.f;
                    s->BIt[(e0 + 1) * TILE_P + pl] = 0.f;
                    s->BIt[(e0 + 2) * TILE_P + pl] = 0.f;
                    s->BIt[(e0 + 3) * TILE_P + pl] = 0.f;
                }
            }
        }
        __syncthreads();

        // --- register-tiled GEMM: 4 pairs x 8 a per thread ---
        // acc[q][t] packs (a0+2t, a0+2t+1) for pair q. Bias in the init.
        u64 acc[4][4];
        #pragma unroll
        for (int q = 0; q < 4; q++) {
            acc[q][0] = bini0.x;
            acc[q][1] = bini0.y;
            acc[q][2] = bini1.x;
            acc[q][3] = bini1.y;
        }

        #pragma unroll 4
        for (int e = 0; e < EDIM; e++) {
            float4 bv = *(const float4*)(s->BIt + e * TILE_P + p_off); // 1 wf/warp
            u64 b0 = pack2(bv.x);
            u64 b1 = pack2(bv.y);
            u64 b2 = pack2(bv.z);
            u64 b3 = pack2(bv.w);
            const ulonglong2* wp = (const ulonglong2*)(s->Ws + e * ADIM + a0);
            ulonglong2 wA = wp[0];     // (w[a0],w[a0+1]),(w[a0+2],w[a0+3])
            ulonglong2 wB = wp[1];
            acc[0][0] = fma2(b0, wA.x, acc[0][0]);
            acc[0][1] = fma2(b0, wA.y, acc[0][1]);
            acc[0][2] = fma2(b0, wB.x, acc[0][2]);
            acc[0][3] = fma2(b0, wB.y, acc[0][3]);
            acc[1][0] = fma2(b1, wA.x, acc[1][0]);
            acc[1][1] = fma2(b1, wA.y, acc[1][1]);
            acc[1][2] = fma2(b1, wB.x, acc[1][2]);
            acc[1][3] = fma2(b1, wB.y, acc[1][3]);
            acc[2][0] = fma2(b2, wA.x, acc[2][0]);
            acc[2][1] = fma2(b2, wA.y, acc[2][1]);
            acc[2][2] = fma2(b2, wB.x, acc[2][2]);
            acc[2][3] = fma2(b2, wB.y, acc[2][3]);
            acc[3][0] = fma2(b3, wA.x, acc[3][0]);
            acc[3][1] = fma2(b3, wA.y, acc[3][1]);
            acc[3][2] = fma2(b3, wB.x, acc[3][2]);
            acc[3][3] = fma2(b3, wB.y, acc[3][3]);
        }

        // --- epilogue: relu(z).h over 8 a, then shuffle-reduce the 4 ag ---
        float sq[4];
        #pragma unroll
        for (int q = 0; q < 4; q++) {
            float acc_s = 0.f;
            #pragma unroll
            for (int t = 0; t < 4; t++) {
                int a = a0 + 2 * t;
                acc_s = fmaf(fmaxf(lo32(acc[q][t]), 0.f), s->hs[a],     acc_s);
                acc_s = fmaf(fmaxf(hi32(acc[q][t]), 0.f), s->hs[a + 1], acc_s);
            }
            // reduce over ag_w (lane bits 3,4)
            acc_s += __shfl_xor_sync(0xffffffffu, acc_s, 8);
            acc_s += __shfl_xor_sync(0xffffffffu, acc_s, 16);
            sq[q] = acc_s;
        }
        if (ag_w == 0) {
            #pragma unroll
            for (int q = 0; q < 4; q++)
                s->scpart[(p_off + q) * 2 + ablk] = sq[q];
        }
        __syncthreads();

        // --- combine the 2 a-block partials into the score ---
        if (tid < TILE_P) {
            int p = tile * TILE_P + tid;
            if (p < NPAIR)
                s->sc[p] = s->scpart[tid * 2] + s->scpart[tid * 2 + 1];
        }
        __syncthreads();
    }

    // ---------------- Phase 2: softmax over 780 scores ----------------
    float m = -3.402823466e38f;
    for (int p = tid; p < NPAIR; p += NT) m = fmaxf(m, s->sc[p]);
    #pragma unroll
    for (int o = 16; o; o >>= 1) m = fmaxf(m, __shfl_xor_sync(0xffffffffu, m, o));
    if ((tid & 31) == 0) s->red[tid >> 5] = m;
    __syncthreads();
    if (tid == 0) {
        float mm = s->red[0];
        #pragma unroll
        for (int w = 1; w < 8; w++) mm = fmaxf(mm, s->red[w]);
        s->red[0] = mm;
    }
    __syncthreads();
    m = s->red[0];
    __syncthreads();

    float sum = 0.f;
    for (int p = tid; p < NPAIR; p += NT) {
        float e0 = __expf(s->sc[p] - m);
        s->sc[p] = e0;
        sum += e0;
    }
    #pragma unroll
    for (int o = 16; o; o >>= 1) sum += __shfl_xor_sync(0xffffffffu, sum, o);
    if ((tid & 31) == 0) s->red[tid >> 5] = sum;
    __syncthreads();
    if (tid == 0) {
        float ss = s->red[0];
        #pragma unroll
        for (int w = 1; w < 8; w++) ss += s->red[w];
        s->red[0] = ss;
    }
    __syncthreads();
    const float scale = (float)NPAIR / s->red[0];

    // ---------------- Phase 3: weighted pooling + final dot ----------------
    {
        const int e = tid & 63;
        const int g = tid >> 6;
        float acc = 0.f;
        for (int p = g; p < NPAIR; p += 4) {
            float w = s->sc[p];
            int   i = s->pii[p];
            int   j = s->pjj[p];
            acc = fmaf(w, s->xs[i * EDIM + e] * s->xs[j * EDIM + e], acc);
        }
        s->partial[g * EDIM + e] = acc;
    }
    __syncthreads();
    if (tid < EDIM) {
        float pooled = (s->partial[tid] + s->partial[EDIM + tid]) +
                       (s->partial[2 * EDIM + tid] + s->partial[3 * EDIM + tid]);
        s->partial[tid] = pooled * scale * s->pws[tid];
    }
    __syncthreads();
    if (tid < 32) {
        float v = s->partial[tid] + s->partial[tid + 32];
        #pragma unroll
        for (int o = 16; o; o >>= 1) v += __shfl_xor_sync(0xffffffffu, v, o);
        if (tid == 0) out[b] = v;
    }
}

extern "C" void kernel_launch(void* const* d_in, const int* in_sizes, int n_in,
                              void* d_out, int out_size) {
    const float* x    = (const float*)d_in[0];
    const float* W    = (const float*)d_in[1];
    const float* bias = (const float*)d_in[2];
    const float* h    = (const float*)d_in[3];
    const float* pw   = (const float*)d_in[4];
    float* out = (float*)d_out;

    int B = in_sizes[0] / (FEAT * EDIM);
    size_t smem_bytes = sizeof(Smem);

    static bool attr_set = false;
    if (!attr_set) {
        cudaFuncSetAttribute(afm_main_kernel,
                             cudaFuncAttributeMaxDynamicSharedMemorySize,
                             (int)smem_bytes);
        attr_set = true;
    }

    afm_main_kernel<<<B, NT, smem_bytes>>>(x, W, bias, h, pw, out);
}

// round 6
// speedup vs baseline: 3.6497x; 2.3204x over previous
#include <cuda_runtime.h>
#include <cuda_fp16.h>
#include <cstdint>
#include <cstring>

#define FEAT   40
#define EDIM   64
#define ADIM   64
#define NPAIR  780          // FEAT*(FEAT-1)/2
#define NT     256
#define TILE_P 128
#define NTILES 7            // ceil(780/128)
#define XS_STRIDE 68        // padded x row

// ---------------------------------------------------------------------------
// m16n8k16 fp16 MMA with f32 accumulation (arch-generic, works on sm_100)
// ---------------------------------------------------------------------------
__device__ __forceinline__ void mma_fp16(float d[4],
                                         uint32_t a0, uint32_t a1,
                                         uint32_t a2, uint32_t a3,
                                         uint32_t b0, uint32_t b1) {
    asm volatile(
        "mma.sync.aligned.m16n8k16.row.col.f32.f16.f16.f32 "
        "{%0,%1,%2,%3}, {%4,%5,%6,%7}, {%8,%9}, {%0,%1,%2,%3};"
        : "+f"(d[0]), "+f"(d[1]), "+f"(d[2]), "+f"(d[3])
        : "r"(a0), "r"(a1), "r"(a2), "r"(a3), "r"(b0), "r"(b1));
}

__device__ __forceinline__ uint32_t h2u(__half2 h) {
    uint32_t u;
    memcpy(&u, &h, 4);
    return u;
}

struct __align__(16) Smem {
    float xs[FEAT * XS_STRIDE];   // 10880
    uint2 Whf[4 * 8 * 32];        // 8192  W-hi fragments [eblk][ablk][lane]
    uint2 Wlf[4 * 8 * 32];        // 8192  W-lo fragments
    float sc[NPAIR];              // 3120
    float partial[4 * EDIM];      // 1024
    float bs[ADIM];
    float hs[ADIM];
    float pws[EDIM];
    float red[8];
    unsigned char pii[NPAIR];
    unsigned char pjj[NPAIR];
};

__global__ __launch_bounds__(NT, 2)
void afm_main_kernel(const float* __restrict__ x,
                     const float* __restrict__ W,
                     const float* __restrict__ bias,
                     const float* __restrict__ h,
                     const float* __restrict__ pw,
                     float* __restrict__ out) {
    extern __shared__ char smem_raw[];
    Smem* s = reinterpret_cast<Smem*>(smem_raw);

    const int b    = blockIdx.x;
    const int tid  = threadIdx.x;
    const int wid  = tid >> 5;
    const int lane = tid & 31;

    // ---------------- Phase 0: stage inputs + W fragment build ----------
    {
        const float* xb = x + (long)b * FEAT * EDIM;
        for (int idx = tid; idx < FEAT * EDIM; idx += NT) {
            int row = idx >> 6, col = idx & 63;
            s->xs[row * XS_STRIDE + col] = xb[idx];
        }
        // B fragments for m16n8k16: per (eblk, ablk, lane):
        //   n = 8*ablk + lane/4 ; k0 = 16*eblk + (lane%4)*2
        //   b0 = halves (W[k0][n], W[k0+1][n]) ; b1 = (W[k0+8][n], W[k0+9][n])
        for (int idx = tid; idx < 4 * 8 * 32; idx += NT) {
            int l    = idx & 31;
            int ablk = (idx >> 5) & 7;
            int eblk = idx >> 8;
            int n  = 8 * ablk + (l >> 2);
            int k0 = 16 * eblk + (l & 3) * 2;
            float w00 = W[(k0    ) * ADIM + n];
            float w01 = W[(k0 + 1) * ADIM + n];
            float w10 = W[(k0 + 8) * ADIM + n];
            float w11 = W[(k0 + 9) * ADIM + n];
            __half2 h0 = __floats2half2_rn(w00, w01);
            __half2 h1 = __floats2half2_rn(w10, w11);
            float2 f0 = __half22float2(h0);
            float2 f1 = __half22float2(h1);
            __half2 l0 = __floats2half2_rn(w00 - f0.x, w01 - f0.y);
            __half2 l1 = __floats2half2_rn(w10 - f1.x, w11 - f1.y);
            s->Whf[idx] = make_uint2(h2u(h0), h2u(h1));
            s->Wlf[idx] = make_uint2(h2u(l0), h2u(l1));
        }
        if (tid < ADIM) { s->bs[tid] = bias[tid]; s->hs[tid] = h[tid]; }
        if (tid < EDIM) s->pws[tid] = pw[tid];
        if (tid < FEAT - 1) {
            int i = tid;
            int base = i * (FEAT - 1) - i * (i - 1) / 2;
            for (int j = i + 1; j < FEAT; j++) {
                s->pii[base + j - i - 1] = (unsigned char)i;
                s->pjj[base + j - i - 1] = (unsigned char)j;
            }
        }
    }
    __syncthreads();

    const int r  = lane >> 2;        // row-within-16 (0..7); rows r, r+8
    const int c0 = (lane & 3) * 2;   // col pair base

    // ---------------- Phase 1: warp-independent fp16-split MMA ----------
    for (int tile = 0; tile < NTILES; tile++) {
        const int pbase = tile * TILE_P + wid * 16;
        if (pbase >= NPAIR) continue;     // whole warp-slice out of range

        const int p0 = pbase + r;
        const int p1 = p0 + 8;
        const int i0 = (p0 < NPAIR) ? s->pii[p0] : 0;
        const int j0 = (p0 < NPAIR) ? s->pjj[p0] : 0;
        const int i1 = (p1 < NPAIR) ? s->pii[p1] : 0;
        const int j1 = (p1 < NPAIR) ? s->pjj[p1] : 0;
        const float* xi0 = s->xs + i0 * XS_STRIDE;
        const float* xj0 = s->xs + j0 * XS_STRIDE;
        const float* xi1 = s->xs + i1 * XS_STRIDE;
        const float* xj1 = s->xs + j1 * XS_STRIDE;

        // --- build A fragments (hi + lo) for 4 eblks ---
        uint32_t ah[4][4], al[4][4];
        #pragma unroll
        for (int eb = 0; eb < 4; eb++) {
            int e = 16 * eb + c0;
            // row r0: frags a0 (cols c0,c0+1), a2 (cols c0+8,c0+9)
            {
                float2 xa = *(const float2*)(xi0 + e);
                float2 xb2 = *(const float2*)(xj0 + e);
                float pA0 = xa.x * xb2.x, pA1 = xa.y * xb2.y;
                float2 xc = *(const float2*)(xi0 + e + 8);
                float2 xd = *(const float2*)(xj0 + e + 8);
                float pB0 = xc.x * xd.x, pB1 = xc.y * xd.y;
                __half2 hA = __floats2half2_rn(pA0, pA1);
                __half2 hB = __floats2half2_rn(pB0, pB1);
                float2 fA = __half22float2(hA);
                float2 fB = __half22float2(hB);
                __half2 lA = __floats2half2_rn(pA0 - fA.x, pA1 - fA.y);
                __half2 lB = __floats2half2_rn(pB0 - fB.x, pB1 - fB.y);
                ah[eb][0] = h2u(hA); ah[eb][2] = h2u(hB);
                al[eb][0] = h2u(lA); al[eb][2] = h2u(lB);
            }
            // row r1 = r0+8: frags a1, a3
            {
                float2 xa = *(const float2*)(xi1 + e);
                float2 xb2 = *(const float2*)(xj1 + e);
                float pA0 = xa.x * xb2.x, pA1 = xa.y * xb2.y;
                float2 xc = *(const float2*)(xi1 + e + 8);
                float2 xd = *(const float2*)(xj1 + e + 8);
                float pB0 = xc.x * xd.x, pB1 = xc.y * xd.y;
                __half2 hA = __floats2half2_rn(pA0, pA1);
                __half2 hB = __floats2half2_rn(pB0, pB1);
                float2 fA = __half22float2(hA);
                float2 fB = __half22float2(hB);
                __half2 lA = __floats2half2_rn(pA0 - fA.x, pA1 - fA.y);
                __half2 lB = __floats2half2_rn(pB0 - fB.x, pB1 - fB.y);
                ah[eb][1] = h2u(hA); ah[eb][3] = h2u(hB);
                al[eb][1] = h2u(lA); al[eb][3] = h2u(lB);
            }
        }

        // --- D accumulators, bias-initialized ---
        float d[8][4];
        #pragma unroll
        for (int ab = 0; ab < 8; ab++) {
            float b0v = s->bs[8 * ab + c0];
            float b1v = s->bs[8 * ab + c0 + 1];
            d[ab][0] = b0v; d[ab][1] = b1v;
            d[ab][2] = b0v; d[ab][3] = b1v;
        }

        // --- 3 passes: hi*Whi, lo*Whi, hi*Wlo ---
        #pragma unroll
        for (int pass = 0; pass < 3; pass++) {
            const uint2* Wf = (pass == 2) ? s->Wlf : s->Whf;
            #pragma unroll
            for (int eb = 0; eb < 4; eb++) {
                const uint32_t* A = (pass == 1) ? al[eb] : ah[eb];
                #pragma unroll
                for (int ab = 0; ab < 8; ab++) {
                    uint2 bf = Wf[(eb * 8 + ab) * 32 + lane];
                    mma_fp16(d[ab], A[0], A[1], A[2], A[3], bf.x, bf.y);
                }
            }
        }

        // --- epilogue: relu(z)·h, reduce 4 lanes per row ---
        float s0 = 0.f, s1 = 0.f;
        #pragma unroll
        for (int ab = 0; ab < 8; ab++) {
            int a = 8 * ab + c0;
            float h0v = s->hs[a], h1v = s->hs[a + 1];
            s0 = fmaf(fmaxf(d[ab][0], 0.f), h0v, s0);
            s0 = fmaf(fmaxf(d[ab][1], 0.f), h1v, s0);
            s1 = fmaf(fmaxf(d[ab][2], 0.f), h0v, s1);
            s1 = fmaf(fmaxf(d[ab][3], 0.f), h1v, s1);
        }
        s0 += __shfl_xor_sync(0xffffffffu, s0, 1);
        s0 += __shfl_xor_sync(0xffffffffu, s0, 2);
        s1 += __shfl_xor_sync(0xffffffffu, s1, 1);
        s1 += __shfl_xor_sync(0xffffffffu, s1, 2);
        if ((lane & 3) == 0) {
            if (p0 < NPAIR) s->sc[p0] = s0;
            if (p1 < NPAIR) s->sc[p1] = s1;
        }
    }
    __syncthreads();

    // ---------------- Phase 2: softmax over 780 scores ----------------
    float m = -3.402823466e38f;
    for (int p = tid; p < NPAIR; p += NT) m = fmaxf(m, s->sc[p]);
    #pragma unroll
    for (int o = 16; o; o >>= 1) m = fmaxf(m, __shfl_xor_sync(0xffffffffu, m, o));
    if (lane == 0) s->red[wid] = m;
    __syncthreads();
    if (tid == 0) {
        float mm = s->red[0];
        #pragma unroll
        for (int w = 1; w < 8; w++) mm = fmaxf(mm, s->red[w]);
        s->red[0] = mm;
    }
    __syncthreads();
    m = s->red[0];
    __syncthreads();

    float sum = 0.f;
    for (int p = tid; p < NPAIR; p += NT) {
        float e0 = __expf(s->sc[p] - m);
        s->sc[p] = e0;
        sum += e0;
    }
    #pragma unroll
    for (int o = 16; o; o >>= 1) sum += __shfl_xor_sync(0xffffffffu, sum, o);
    if (lane == 0) s->red[wid] = sum;
    __syncthreads();
    if (tid == 0) {
        float ss = s->red[0];
        #pragma unroll
        for (int w = 1; w < 8; w++) ss += s->red[w];
        s->red[0] = ss;
    }
    __syncthreads();
    const float scale = (float)NPAIR / s->red[0];

    // ---------------- Phase 3: weighted pooling + final dot ------------
    {
        const int e = tid & 63;
        const int g = tid >> 6;
        float acc = 0.f;
        for (int p = g; p < NPAIR; p += 4) {
            float w = s->sc[p];
            int   i = s->pii[p];
            int   j = s->pjj[p];
            acc = fmaf(w, s->xs[i * XS_STRIDE + e] * s->xs[j * XS_STRIDE + e], acc);
        }
        s->partial[g * EDIM + e] = acc;
    }
    __syncthreads();
    if (tid < EDIM) {
        float pooled = (s->partial[tid] + s->partial[EDIM + tid]) +
                       (s->partial[2 * EDIM + tid] + s->partial[3 * EDIM + tid]);
        s->partial[tid] = pooled * scale * s->pws[tid];
    }
    __syncthreads();
    if (tid < 32) {
        float v = s->partial[tid] + s->partial[tid + 32];
        #pragma unroll
        for (int o = 16; o; o >>= 1) v += __shfl_xor_sync(0xffffffffu, v, o);
        if (tid == 0) out[b] = v;
    }
}

extern "C" void kernel_launch(void* const* d_in, const int* in_sizes, int n_in,
                              void* d_out, int out_size) {
    const float* x    = (const float*)d_in[0];
    const float* W    = (const float*)d_in[1];
    const float* bias = (const float*)d_in[2];
    const float* h    = (const float*)d_in[3];
    const float* pw   = (const float*)d_in[4];
    float* out = (float*)d_out;

    int B = in_sizes[0] / (FEAT * EDIM);
    size_t smem_bytes = sizeof(Smem);

    static bool attr_set = false;
    if (!attr_set) {
        cudaFuncSetAttribute(afm_main_kernel,
                             cudaFuncAttributeMaxDynamicSharedMemorySize,
                             (int)smem_bytes);
        attr_set = true;
    }

    afm_main_kernel<<<B, NT, smem_bytes>>>(x, W, bias, h, pw, out);
}

// round 7
// speedup vs baseline: 3.8914x; 1.0662x over previous
#include <cuda_runtime.h>
#include <cuda_fp16.h>
#include <cstdint>
#include <cstring>

#define FEAT   40
#define EDIM   64
#define ADIM   64
#define NPAIR  780          // FEAT*(FEAT-1)/2
#define NT     256
#define SUPER_P 256         // pairs per supertile (8 warps x 32)
#define NSUPER  4           // ceil(780/256)
#define XS_STRIDE 68        // padded x row

// ---------------------------------------------------------------------------
// m16n8k16 fp16 MMA with f32 accumulation (arch-generic, works on sm_100)
// ---------------------------------------------------------------------------
__device__ __forceinline__ void mma_fp16(float d[4],
                                         uint32_t a0, uint32_t a1,
                                         uint32_t a2, uint32_t a3,
                                         uint32_t b0, uint32_t b1) {
    asm volatile(
        "mma.sync.aligned.m16n8k16.row.col.f32.f16.f16.f32 "
        "{%0,%1,%2,%3}, {%4,%5,%6,%7}, {%8,%9}, {%0,%1,%2,%3};"
        : "+f"(d[0]), "+f"(d[1]), "+f"(d[2]), "+f"(d[3])
        : "r"(a0), "r"(a1), "r"(a2), "r"(a3), "r"(b0), "r"(b1));
}

__device__ __forceinline__ uint32_t h2u(__half2 h) {
    uint32_t u;
    memcpy(&u, &h, 4);
    return u;
}

struct __align__(16) Smem {
    float xs[FEAT * XS_STRIDE];   // 10880
    uint2 Whf[4 * 8 * 32];        // 8192  W-hi fragments [eblk][ablk][lane]
    uint2 Wlf[4 * 8 * 32];        // 8192  W-lo fragments
    float sc[NPAIR];              // 3120
    float partial[4 * EDIM];      // 1024
    float bs[ADIM];
    float hs[ADIM];
    float pws[EDIM];
    float red[8];
    unsigned char pii[NPAIR];
    unsigned char pjj[NPAIR];
};

__global__ __launch_bounds__(NT, 2)
void afm_main_kernel(const float* __restrict__ x,
                     const float* __restrict__ W,
                     const float* __restrict__ bias,
                     const float* __restrict__ h,
                     const float* __restrict__ pw,
                     float* __restrict__ out) {
    extern __shared__ char smem_raw[];
    Smem* s = reinterpret_cast<Smem*>(smem_raw);

    const int b    = blockIdx.x;
    const int tid  = threadIdx.x;
    const int wid  = tid >> 5;
    const int lane = tid & 31;

    // ---------------- Phase 0: stage inputs + W fragment build ----------
    {
        const float* xb = x + (long)b * FEAT * EDIM;
        for (int idx = tid; idx < FEAT * EDIM; idx += NT) {
            int row = idx >> 6, col = idx & 63;
            s->xs[row * XS_STRIDE + col] = xb[idx];
        }
        // B fragments for m16n8k16: per (eblk, ablk, lane):
        //   n = 8*ablk + lane/4 ; k0 = 16*eblk + (lane%4)*2
        for (int idx = tid; idx < 4 * 8 * 32; idx += NT) {
            int l    = idx & 31;
            int ablk = (idx >> 5) & 7;
            int eblk = idx >> 8;
            int n  = 8 * ablk + (l >> 2);
            int k0 = 16 * eblk + (l & 3) * 2;
            float w00 = W[(k0    ) * ADIM + n];
            float w01 = W[(k0 + 1) * ADIM + n];
            float w10 = W[(k0 + 8) * ADIM + n];
            float w11 = W[(k0 + 9) * ADIM + n];
            __half2 h0 = __floats2half2_rn(w00, w01);
            __half2 h1 = __floats2half2_rn(w10, w11);
            float2 f0 = __half22float2(h0);
            float2 f1 = __half22float2(h1);
            __half2 l0 = __floats2half2_rn(w00 - f0.x, w01 - f0.y);
            __half2 l1 = __floats2half2_rn(w10 - f1.x, w11 - f1.y);
            s->Whf[idx] = make_uint2(h2u(h0), h2u(h1));
            s->Wlf[idx] = make_uint2(h2u(l0), h2u(l1));
        }
        if (tid < ADIM) { s->bs[tid] = bias[tid]; s->hs[tid] = h[tid]; }
        if (tid < EDIM) s->pws[tid] = pw[tid];
        if (tid < FEAT - 1) {
            int i = tid;
            int base = i * (FEAT - 1) - i * (i - 1) / 2;
            for (int j = i + 1; j < FEAT; j++) {
                s->pii[base + j - i - 1] = (unsigned char)i;
                s->pjj[base + j - i - 1] = (unsigned char)j;
            }
        }
    }
    __syncthreads();

    const int r  = lane >> 2;        // row-within-16 (0..7)
    const int c0 = (lane & 3) * 2;   // col pair base

    // ---------------- Phase 1: warp-independent fp16-split MMA ----------
    // Each warp owns 32 pairs per supertile: two m16 blocks.
    for (int st = 0; st < NSUPER; st++) {
        const int pbase = st * SUPER_P + wid * 32;
        if (pbase >= NPAIR) continue;

        // pair rows for the 2 m-blocks: mb rows = pbase + 16*mb + r (+8)
        int prow[4];                  // [mb*2 + (0:r,1:r+8)]
        const float *xi[4], *xj[4];
        #pragma unroll
        for (int q = 0; q < 4; q++) {
            int p = pbase + 16 * (q >> 1) + r + 8 * (q & 1);
            prow[q] = p;
            int ii = (p < NPAIR) ? s->pii[p] : 0;
            int jj = (p < NPAIR) ? s->pjj[p] : 0;
            xi[q] = s->xs + ii * XS_STRIDE;
            xj[q] = s->xs + jj * XS_STRIDE;
        }

        // D accumulators, bias-initialized: d[mb][ab][4]
        float d[2][8][4];
        #pragma unroll
        for (int mb = 0; mb < 2; mb++)
            #pragma unroll
            for (int ab = 0; ab < 8; ab++) {
                float b0v = s->bs[8 * ab + c0];
                float b1v = s->bs[8 * ab + c0 + 1];
                d[mb][ab][0] = b0v; d[mb][ab][1] = b1v;
                d[mb][ab][2] = b0v; d[mb][ab][3] = b1v;
            }

        #pragma unroll
        for (int eb = 0; eb < 4; eb++) {
            const int e = 16 * eb + c0;
            // --- build A fragments for this eblk: 2 m-blocks, hi + lo ---
            uint32_t ah[2][4], al[2][4];
            #pragma unroll
            for (int mb = 0; mb < 2; mb++) {
                #pragma unroll
                for (int rr = 0; rr < 2; rr++) {       // rr=0: row r, rr=1: r+8
                    const float* pxi = xi[mb * 2 + rr];
                    const float* pxj = xj[mb * 2 + rr];
                    float2 xa  = *(const float2*)(pxi + e);
                    float2 xb2 = *(const float2*)(pxj + e);
                    float pA0 = xa.x * xb2.x, pA1 = xa.y * xb2.y;
                    float2 xc = *(const float2*)(pxi + e + 8);
                    float2 xd = *(const float2*)(pxj + e + 8);
                    float pB0 = xc.x * xd.x, pB1 = xc.y * xd.y;
                    __half2 hA = __floats2half2_rn(pA0, pA1);
                    __half2 hB = __floats2half2_rn(pB0, pB1);
                    float2 fA = __half22float2(hA);
                    float2 fB = __half22float2(hB);
                    __half2 lA = __floats2half2_rn(pA0 - fA.x, pA1 - fA.y);
                    __half2 lB = __floats2half2_rn(pB0 - fB.x, pB1 - fB.y);
                    ah[mb][rr]     = h2u(hA);
                    ah[mb][rr + 2] = h2u(hB);
                    al[mb][rr]     = h2u(lA);
                    al[mb][rr + 2] = h2u(lB);
                }
            }
            // --- MMAs: share each B-hi fragment across hi & lo A passes ---
            #pragma unroll
            for (int ab = 0; ab < 8; ab++) {
                uint2 bfh = s->Whf[(eb * 8 + ab) * 32 + lane];
                mma_fp16(d[0][ab], ah[0][0], ah[0][1], ah[0][2], ah[0][3], bfh.x, bfh.y);
                mma_fp16(d[1][ab], ah[1][0], ah[1][1], ah[1][2], ah[1][3], bfh.x, bfh.y);
                mma_fp16(d[0][ab], al[0][0], al[0][1], al[0][2], al[0][3], bfh.x, bfh.y);
                mma_fp16(d[1][ab], al[1][0], al[1][1], al[1][2], al[1][3], bfh.x, bfh.y);
            }
            #pragma unroll
            for (int ab = 0; ab < 8; ab++) {
                uint2 bfl = s->Wlf[(eb * 8 + ab) * 32 + lane];
                mma_fp16(d[0][ab], ah[0][0], ah[0][1], ah[0][2], ah[0][3], bfl.x, bfl.y);
                mma_fp16(d[1][ab], ah[1][0], ah[1][1], ah[1][2], ah[1][3], bfl.x, bfl.y);
            }
        }

        // --- epilogue: relu(z)·h, reduce 4 lanes per row ---
        #pragma unroll
        for (int mb = 0; mb < 2; mb++) {
            float s0 = 0.f, s1 = 0.f;
            #pragma unroll
            for (int ab = 0; ab < 8; ab++) {
                int a = 8 * ab + c0;
                float h0v = s->hs[a], h1v = s->hs[a + 1];
                s0 = fmaf(fmaxf(d[mb][ab][0], 0.f), h0v, s0);
                s0 = fmaf(fmaxf(d[mb][ab][1], 0.f), h1v, s0);
                s1 = fmaf(fmaxf(d[mb][ab][2], 0.f), h0v, s1);
                s1 = fmaf(fmaxf(d[mb][ab][3], 0.f), h1v, s1);
            }
            s0 += __shfl_xor_sync(0xffffffffu, s0, 1);
            s0 += __shfl_xor_sync(0xffffffffu, s0, 2);
            s1 += __shfl_xor_sync(0xffffffffu, s1, 1);
            s1 += __shfl_xor_sync(0xffffffffu, s1, 2);
            if ((lane & 3) == 0) {
                int p0 = prow[mb * 2];
                int p1 = prow[mb * 2 + 1];
                if (p0 < NPAIR) s->sc[p0] = s0;
                if (p1 < NPAIR) s->sc[p1] = s1;
            }
        }
    }
    __syncthreads();

    // ---------------- Phase 2: softmax over 780 scores ----------------
    float m = -3.402823466e38f;
    for (int p = tid; p < NPAIR; p += NT) m = fmaxf(m, s->sc[p]);
    #pragma unroll
    for (int o = 16; o; o >>= 1) m = fmaxf(m, __shfl_xor_sync(0xffffffffu, m, o));
    if (lane == 0) s->red[wid] = m;
    __syncthreads();
    if (tid == 0) {
        float mm = s->red[0];
        #pragma unroll
        for (int w = 1; w < 8; w++) mm = fmaxf(mm, s->red[w]);
        s->red[0] = mm;
    }
    __syncthreads();
    m = s->red[0];
    __syncthreads();

    float sum = 0.f;
    for (int p = tid; p < NPAIR; p += NT) {
        float e0 = __expf(s->sc[p] - m);
        s->sc[p] = e0;
        sum += e0;
    }
    #pragma unroll
    for (int o = 16; o; o >>= 1) sum += __shfl_xor_sync(0xffffffffu, sum, o);
    if (lane == 0) s->red[wid] = sum;
    __syncthreads();
    if (tid == 0) {
        float ss = s->red[0];
        #pragma unroll
        for (int w = 1; w < 8; w++) ss += s->red[w];
        s->red[0] = ss;
    }
    __syncthreads();
    const float scale = (float)NPAIR / s->red[0];

    // ---------------- Phase 3: weighted pooling + final dot ------------
    {
        const int e = tid & 63;
        const int g = tid >> 6;
        float acc = 0.f;
        for (int p = g; p < NPAIR; p += 4) {
            float w = s->sc[p];
            int   i = s->pii[p];
            int   j = s->pjj[p];
            acc = fmaf(w, s->xs[i * XS_STRIDE + e] * s->xs[j * XS_STRIDE + e], acc);
        }
        s->partial[g * EDIM + e] = acc;
    }
    __syncthreads();
    if (tid < EDIM) {
        float pooled = (s->partial[tid] + s->partial[EDIM + tid]) +
                       (s->partial[2 * EDIM + tid] + s->partial[3 * EDIM + tid]);
        s->partial[tid] = pooled * scale * s->pws[tid];
    }
    __syncthreads();
    if (tid < 32) {
        float v = s->partial[tid] + s->partial[tid + 32];
        #pragma unroll
        for (int o = 16; o; o >>= 1) v += __shfl_xor_sync(0xffffffffu, v, o);
        if (tid == 0) out[b] = v;
    }
}

extern "C" void kernel_launch(void* const* d_in, const int* in_sizes, int n_in,
                              void* d_out, int out_size) {
    const float* x    = (const float*)d_in[0];
    const float* W    = (const float*)d_in[1];
    const float* bias = (const float*)d_in[2];
    const float* h    = (const float*)d_in[3];
    const float* pw   = (const float*)d_in[4];
    float* out = (float*)d_out;

    int B = in_sizes[0] / (FEAT * EDIM);
    size_t smem_bytes = sizeof(Smem);

    static bool attr_set = false;
    if (!attr_set) {
        cudaFuncSetAttribute(afm_main_kernel,
                             cudaFuncAttributeMaxDynamicSharedMemorySize,
                             (int)smem_bytes);
        attr_set = true;
    }

    afm_main_kernel<<<B, NT, smem_bytes>>>(x, W, bias, h, pw, out);
}

// round 8
// speedup vs baseline: 3.9816x; 1.0232x over previous
#include <cuda_runtime.h>
#include <cuda_fp16.h>
#include <cstdint>
#include <cstring>

#define FEAT   40
#define EDIM   64
#define ADIM   64
#define NPAIR  780          // FEAT*(FEAT-1)/2
#define NT     256
#define SUPER_P 256         // pairs per supertile (8 warps x 32)
#define NSUPER  4           // ceil(780/256)
#define XS_STRIDE 68        // padded x row

// ---------------------------------------------------------------------------
// m16n8k16 fp16 MMA with f32 accumulation (arch-generic, works on sm_100)
// ---------------------------------------------------------------------------
__device__ __forceinline__ void mma_fp16(float d[4],
                                         uint32_t a0, uint32_t a1,
                                         uint32_t a2, uint32_t a3,
                                         uint32_t b0, uint32_t b1) {
    asm volatile(
        "mma.sync.aligned.m16n8k16.row.col.f32.f16.f16.f32 "
        "{%0,%1,%2,%3}, {%4,%5,%6,%7}, {%8,%9}, {%0,%1,%2,%3};"
        : "+f"(d[0]), "+f"(d[1]), "+f"(d[2]), "+f"(d[3])
        : "r"(a0), "r"(a1), "r"(a2), "r"(a3), "r"(b0), "r"(b1));
}

__device__ __forceinline__ uint32_t h2u(__half2 h) {
    uint32_t u;
    memcpy(&u, &h, 4);
    return u;
}

struct __align__(16) Smem {
    float xs[FEAT * XS_STRIDE];   // 10880
    uint2 Whf[4 * 8 * 32];        // 8192  W-hi fragments [eblk][ablk][lane]
    uint2 Wlf[4 * 8 * 32];        // 8192  W-lo fragments
    float sc[NPAIR];              // 3120
    float partial[4 * EDIM];      // 1024
    float bs[ADIM];
    float hs[ADIM];
    float pws[EDIM];
    float red[8];
    unsigned char pii[NPAIR];
    unsigned char pjj[NPAIR];
};

__global__ __launch_bounds__(NT, 2)
void afm_main_kernel(const float* __restrict__ x,
                     const float* __restrict__ W,
                     const float* __restrict__ bias,
                     const float* __restrict__ h,
                     const float* __restrict__ pw,
                     float* __restrict__ out) {
    extern __shared__ char smem_raw[];
    Smem* s = reinterpret_cast<Smem*>(smem_raw);

    const int b    = blockIdx.x;
    const int tid  = threadIdx.x;
    const int wid  = tid >> 5;
    const int lane = tid & 31;

    // ---------------- Phase 0: stage inputs + W fragment build ----------
    {
        const float* xb = x + (long)b * FEAT * EDIM;
        for (int idx = tid; idx < FEAT * EDIM; idx += NT) {
            int row = idx >> 6, col = idx & 63;
            s->xs[row * XS_STRIDE + col] = xb[idx];
        }
        // B fragments for m16n8k16: per (eblk, ablk, lane):
        //   n = 8*ablk + lane/4 ; k0 = 16*eblk + (lane%4)*2
        for (int idx = tid; idx < 4 * 8 * 32; idx += NT) {
            int l    = idx & 31;
            int ablk = (idx >> 5) & 7;
            int eblk = idx >> 8;
            int n  = 8 * ablk + (l >> 2);
            int k0 = 16 * eblk + (l & 3) * 2;
            float w00 = W[(k0    ) * ADIM + n];
            float w01 = W[(k0 + 1) * ADIM + n];
            float w10 = W[(k0 + 8) * ADIM + n];
            float w11 = W[(k0 + 9) * ADIM + n];
            __half2 h0 = __floats2half2_rn(w00, w01);
            __half2 h1 = __floats2half2_rn(w10, w11);
            float2 f0 = __half22float2(h0);
            float2 f1 = __half22float2(h1);
            __half2 l0 = __floats2half2_rn(w00 - f0.x, w01 - f0.y);
            __half2 l1 = __floats2half2_rn(w10 - f1.x, w11 - f1.y);
            s->Whf[idx] = make_uint2(h2u(h0), h2u(h1));
            s->Wlf[idx] = make_uint2(h2u(l0), h2u(l1));
        }
        if (tid < ADIM) { s->bs[tid] = bias[tid]; s->hs[tid] = h[tid]; }
        if (tid < EDIM) s->pws[tid] = pw[tid];
        if (tid < FEAT - 1) {
            int i = tid;
            int base = i * (FEAT - 1) - i * (i - 1) / 2;
            for (int j = i + 1; j < FEAT; j++) {
                s->pii[base + j - i - 1] = (unsigned char)i;
                s->pjj[base + j - i - 1] = (unsigned char)j;
            }
        }
    }
    __syncthreads();

    const int r  = lane >> 2;        // row-within-16 (0..7)
    const int c0 = (lane & 3) * 2;   // col pair base

    // ---------------- Phase 1: warp-independent fp16-split MMA ----------
    // Each warp owns 32 pairs per supertile: two m16 blocks.
    for (int st = 0; st < NSUPER; st++) {
        const int pbase = st * SUPER_P + wid * 32;
        if (pbase >= NPAIR) continue;

        // pair rows for the 2 m-blocks: mb rows = pbase + 16*mb + r (+8)
        int prow[4];                  // [mb*2 + (0:r,1:r+8)]
        const float *xi[4], *xj[4];
        #pragma unroll
        for (int q = 0; q < 4; q++) {
            int p = pbase + 16 * (q >> 1) + r + 8 * (q & 1);
            prow[q] = p;
            int ii = (p < NPAIR) ? s->pii[p] : 0;
            int jj = (p < NPAIR) ? s->pjj[p] : 0;
            xi[q] = s->xs + ii * XS_STRIDE;
            xj[q] = s->xs + jj * XS_STRIDE;
        }

        // D accumulators, bias-initialized: d[mb][ab][4]
        float d[2][8][4];
        #pragma unroll
        for (int mb = 0; mb < 2; mb++)
            #pragma unroll
            for (int ab = 0; ab < 8; ab++) {
                float b0v = s->bs[8 * ab + c0];
                float b1v = s->bs[8 * ab + c0 + 1];
                d[mb][ab][0] = b0v; d[mb][ab][1] = b1v;
                d[mb][ab][2] = b0v; d[mb][ab][3] = b1v;
            }

        #pragma unroll
        for (int eb = 0; eb < 4; eb++) {
            const int e = 16 * eb + c0;
            // --- build A fragments for this eblk: 2 m-blocks, hi + lo ---
            uint32_t ah[2][4], al[2][4];
            #pragma unroll
            for (int mb = 0; mb < 2; mb++) {
                #pragma unroll
                for (int rr = 0; rr < 2; rr++) {       // rr=0: row r, rr=1: r+8
                    const float* pxi = xi[mb * 2 + rr];
                    const float* pxj = xj[mb * 2 + rr];
                    float2 xa  = *(const float2*)(pxi + e);
                    float2 xb2 = *(const float2*)(pxj + e);
                    float pA0 = xa.x * xb2.x, pA1 = xa.y * xb2.y;
                    float2 xc = *(const float2*)(pxi + e + 8);
                    float2 xd = *(const float2*)(pxj + e + 8);
                    float pB0 = xc.x * xd.x, pB1 = xc.y * xd.y;
                    __half2 hA = __floats2half2_rn(pA0, pA1);
                    __half2 hB = __floats2half2_rn(pB0, pB1);
                    float2 fA = __half22float2(hA);
                    float2 fB = __half22float2(hB);
                    __half2 lA = __floats2half2_rn(pA0 - fA.x, pA1 - fA.y);
                    __half2 lB = __floats2half2_rn(pB0 - fB.x, pB1 - fB.y);
                    ah[mb][rr]     = h2u(hA);
                    ah[mb][rr + 2] = h2u(hB);
                    al[mb][rr]     = h2u(lA);
                    al[mb][rr + 2] = h2u(lB);
                }
            }

            // --- preload all 8 B-hi fragments, then 4 sweeps of 8 MMAs ---
            // Any accumulator's reuse distance is 16 MMAs (was 2).
            uint2 bh[8];
            #pragma unroll
            for (int ab = 0; ab < 8; ab++)
                bh[ab] = s->Whf[(eb * 8 + ab) * 32 + lane];

            #pragma unroll
            for (int ab = 0; ab < 8; ab++)
                mma_fp16(d[0][ab], ah[0][0], ah[0][1], ah[0][2], ah[0][3],
                         bh[ab].x, bh[ab].y);
            #pragma unroll
            for (int ab = 0; ab < 8; ab++)
                mma_fp16(d[1][ab], ah[1][0], ah[1][1], ah[1][2], ah[1][3],
                         bh[ab].x, bh[ab].y);
            #pragma unroll
            for (int ab = 0; ab < 8; ab++)
                mma_fp16(d[0][ab], al[0][0], al[0][1], al[0][2], al[0][3],
                         bh[ab].x, bh[ab].y);
            #pragma unroll
            for (int ab = 0; ab < 8; ab++)
                mma_fp16(d[1][ab], al[1][0], al[1][1], al[1][2], al[1][3],
                         bh[ab].x, bh[ab].y);

            // --- W-lo pass: load-interleaved, both m-blocks per fragment ---
            #pragma unroll
            for (int ab = 0; ab < 8; ab++) {
                uint2 bl = s->Wlf[(eb * 8 + ab) * 32 + lane];
                mma_fp16(d[0][ab], ah[0][0], ah[0][1], ah[0][2], ah[0][3],
                         bl.x, bl.y);
                mma_fp16(d[1][ab], ah[1][0], ah[1][1], ah[1][2], ah[1][3],
                         bl.x, bl.y);
            }
        }

        // --- epilogue: relu(z)·h, reduce 4 lanes per row ---
        #pragma unroll
        for (int mb = 0; mb < 2; mb++) {
            float s0 = 0.f, s1 = 0.f;
            #pragma unroll
            for (int ab = 0; ab < 8; ab++) {
                int a = 8 * ab + c0;
                float h0v = s->hs[a], h1v = s->hs[a + 1];
                s0 = fmaf(fmaxf(d[mb][ab][0], 0.f), h0v, s0);
                s0 = fmaf(fmaxf(d[mb][ab][1], 0.f), h1v, s0);
                s1 = fmaf(fmaxf(d[mb][ab][2], 0.f), h0v, s1);
                s1 = fmaf(fmaxf(d[mb][ab][3], 0.f), h1v, s1);
            }
            s0 += __shfl_xor_sync(0xffffffffu, s0, 1);
            s0 += __shfl_xor_sync(0xffffffffu, s0, 2);
            s1 += __shfl_xor_sync(0xffffffffu, s1, 1);
            s1 += __shfl_xor_sync(0xffffffffu, s1, 2);
            if ((lane & 3) == 0) {
                int p0 = prow[mb * 2];
                int p1 = prow[mb * 2 + 1];
                if (p0 < NPAIR) s->sc[p0] = s0;
                if (p1 < NPAIR) s->sc[p1] = s1;
            }
        }
    }
    __syncthreads();

    // ---------------- Phase 2: softmax over 780 scores ----------------
    float m = -3.402823466e38f;
    for (int p = tid; p < NPAIR; p += NT) m = fmaxf(m, s->sc[p]);
    #pragma unroll
    for (int o = 16; o; o >>= 1) m = fmaxf(m, __shfl_xor_sync(0xffffffffu, m, o));
    if (lane == 0) s->red[wid] = m;
    __syncthreads();
    if (tid == 0) {
        float mm = s->red[0];
        #pragma unroll
        for (int w = 1; w < 8; w++) mm = fmaxf(mm, s->red[w]);
        s->red[0] = mm;
    }
    __syncthreads();
    m = s->red[0];
    __syncthreads();

    float sum = 0.f;
    for (int p = tid; p < NPAIR; p += NT) {
        float e0 = __expf(s->sc[p] - m);
        s->sc[p] = e0;
        sum += e0;
    }
    #pragma unroll
    for (int o = 16; o; o >>= 1) sum += __shfl_xor_sync(0xffffffffu, sum, o);
    if (lane == 0) s->red[wid] = sum;
    __syncthreads();
    if (tid == 0) {
        float ss = s->red[0];
        #pragma unroll
        for (int w = 1; w < 8; w++) ss += s->red[w];
        s->red[0] = ss;
    }
    __syncthreads();
    const float scale = (float)NPAIR / s->red[0];

    // ---------------- Phase 3: weighted pooling + final dot ------------
    {
        const int e = tid & 63;
        const int g = tid >> 6;
        float acc = 0.f;
        for (int p = g; p < NPAIR; p += 4) {
            float w = s->sc[p];
            int   i = s->pii[p];
            int   j = s->pjj[p];
            acc = fmaf(w, s->xs[i * XS_STRIDE + e] * s->xs[j * XS_STRIDE + e], acc);
        }
        s->partial[g * EDIM + e] = acc;
    }
    __syncthreads();
    if (tid < EDIM) {
        float pooled = (s->partial[tid] + s->partial[EDIM + tid]) +
                       (s->partial[2 * EDIM + tid] + s->partial[3 * EDIM + tid]);
        s->partial[tid] = pooled * scale * s->pws[tid];
    }
    __syncthreads();
    if (tid < 32) {
        float v = s->partial[tid] + s->partial[tid + 32];
        #pragma unroll
        for (int o = 16; o; o >>= 1) v += __shfl_xor_sync(0xffffffffu, v, o);
        if (tid == 0) out[b] = v;
    }
}

extern "C" void kernel_launch(void* const* d_in, const int* in_sizes, int n_in,
                              void* d_out, int out_size) {
    const float* x    = (const float*)d_in[0];
    const float* W    = (const float*)d_in[1];
    const float* bias = (const float*)d_in[2];
    const float* h    = (const float*)d_in[3];
    const float* pw   = (const float*)d_in[4];
    float* out = (float*)d_out;

    int B = in_sizes[0] / (FEAT * EDIM);
    size_t smem_bytes = sizeof(Smem);

    static bool attr_set = false;
    if (!attr_set) {
        cudaFuncSetAttribute(afm_main_kernel,
                             cudaFuncAttributeMaxDynamicSharedMemorySize,
                             (int)smem_bytes);
        attr_set = true;
    }

    afm_main_kernel<<<B, NT, smem_bytes>>>(x, W, bias, h, pw, out);
}

// round 9
// speedup vs baseline: 5.5270x; 1.3882x over previous
#include <cuda_runtime.h>
#include <cuda_fp16.h>
#include <cstdint>
#include <cstring>

#define FEAT   40
#define EDIM   64
#define ADIM   64
#define NB     9            // n-blocks: 8 for W (64 cols) + 1 for pw column
#define NPAIR  780          // FEAT*(FEAT-1)/2
#define NT     256
#define SUPER_P 256         // pairs per supertile (8 warps x 32)
#define NSUPER  4           // ceil(780/256)
#define XS_STRIDE 68        // padded x row

// ---------------------------------------------------------------------------
// m16n8k16 fp16 MMA with f32 accumulation (arch-generic, works on sm_100)
// ---------------------------------------------------------------------------
__device__ __forceinline__ void mma_fp16(float d[4],
                                         uint32_t a0, uint32_t a1,
                                         uint32_t a2, uint32_t a3,
                                         uint32_t b0, uint32_t b1) {
    asm volatile(
        "mma.sync.aligned.m16n8k16.row.col.f32.f16.f16.f32 "
        "{%0,%1,%2,%3}, {%4,%5,%6,%7}, {%8,%9}, {%0,%1,%2,%3};"
        : "+f"(d[0]), "+f"(d[1]), "+f"(d[2]), "+f"(d[3])
        : "r"(a0), "r"(a1), "r"(a2), "r"(a3), "r"(b0), "r"(b1));
}

__device__ __forceinline__ uint32_t h2u(__half2 h) {
    uint32_t u;
    memcpy(&u, &h, 4);
    return u;
}

struct __align__(16) Smem {
    float xs[FEAT * XS_STRIDE];   // 10880
    uint2 Whf[4 * NB * 32];       // 9216  W'-hi fragments [eblk][nblk][lane]
    uint2 Wlf[4 * NB * 32];       // 9216  W'-lo fragments
    float sc[NPAIR];              // 3120  scores
    float sq[NPAIR];              // 3120  q_p = BI_p . pw
    float bs[ADIM];
    float hs[ADIM];
    float redm[8];
    float reds[8];
    float redd[8];
    unsigned char pii[NPAIR];
    unsigned char pjj[NPAIR];
};

__global__ __launch_bounds__(NT, 2)
void afm_main_kernel(const float* __restrict__ x,
                     const float* __restrict__ W,
                     const float* __restrict__ bias,
                     const float* __restrict__ h,
                     const float* __restrict__ pw,
                     float* __restrict__ out) {
    extern __shared__ char smem_raw[];
    Smem* s = reinterpret_cast<Smem*>(smem_raw);

    const int b    = blockIdx.x;
    const int tid  = threadIdx.x;
    const int wid  = tid >> 5;
    const int lane = tid & 31;

    // ---------------- Phase 0: stage inputs + W' fragment build ---------
    {
        const float* xb = x + (long)b * FEAT * EDIM;
        for (int idx = tid; idx < FEAT * EDIM; idx += NT) {
            int row = idx >> 6, col = idx & 63;
            s->xs[row * XS_STRIDE + col] = xb[idx];
        }
        // W' = [W | pw | 0...]: per (eblk, nblk, lane):
        //   n = 8*nblk + lane/4 ; k0 = 16*eblk + (lane%4)*2
        for (int idx = tid; idx < 4 * NB * 32; idx += NT) {
            int l    = idx & 31;
            int nblk = (idx >> 5) % NB;
            int eblk = (idx >> 5) / NB;
            int n  = 8 * nblk + (l >> 2);
            int k0 = 16 * eblk + (l & 3) * 2;
            float w00, w01, w10, w11;
            if (n < ADIM) {
                w00 = W[(k0    ) * ADIM + n];
                w01 = W[(k0 + 1) * ADIM + n];
                w10 = W[(k0 + 8) * ADIM + n];
                w11 = W[(k0 + 9) * ADIM + n];
            } else if (n == ADIM) {           // the pw column
                w00 = pw[k0];     w01 = pw[k0 + 1];
                w10 = pw[k0 + 8]; w11 = pw[k0 + 9];
            } else {                           // zero padding cols 65..71
                w00 = w01 = w10 = w11 = 0.f;
            }
            __half2 h0 = __floats2half2_rn(w00, w01);
            __half2 h1 = __floats2half2_rn(w10, w11);
            float2 f0 = __half22float2(h0);
            float2 f1 = __half22float2(h1);
            __half2 l0 = __floats2half2_rn(w00 - f0.x, w01 - f0.y);
            __half2 l1 = __floats2half2_rn(w10 - f1.x, w11 - f1.y);
            s->Whf[idx] = make_uint2(h2u(h0), h2u(h1));
            s->Wlf[idx] = make_uint2(h2u(l0), h2u(l1));
        }
        if (tid < ADIM) { s->bs[tid] = bias[tid]; s->hs[tid] = h[tid]; }
        if (tid < FEAT - 1) {
            int i = tid;
            int base = i * (FEAT - 1) - i * (i - 1) / 2;
            for (int j = i + 1; j < FEAT; j++) {
                s->pii[base + j - i - 1] = (unsigned char)i;
                s->pjj[base + j - i - 1] = (unsigned char)j;
            }
        }
    }
    __syncthreads();

    const int r  = lane >> 2;        // row-within-16 (0..7)
    const int c0 = (lane & 3) * 2;   // col pair base

    // ---------------- Phase 1: warp-independent fp16-split MMA ----------
    // Each warp owns 32 pairs per supertile: two m16 blocks, N=72.
    for (int st = 0; st < NSUPER; st++) {
        const int pbase = st * SUPER_P + wid * 32;
        if (pbase >= NPAIR) continue;

        int prow[4];                  // [mb*2 + (0:r,1:r+8)]
        int ofsI[4], ofsJ[4];         // xs row offsets (32-bit, reg-lean)
        #pragma unroll
        for (int q = 0; q < 4; q++) {
            int p = pbase + 16 * (q >> 1) + r + 8 * (q & 1);
            prow[q] = p;
            int ii = (p < NPAIR) ? s->pii[p] : 0;
            int jj = (p < NPAIR) ? s->pjj[p] : 0;
            ofsI[q] = ii * XS_STRIDE;
            ofsJ[q] = jj * XS_STRIDE;
        }

        // D accumulators: d[mb][nb][4]; bias for nb<8, zero for the q column
        float d[2][NB][4];
        #pragma unroll
        for (int mb = 0; mb < 2; mb++) {
            #pragma unroll
            for (int ab = 0; ab < 8; ab++) {
                float b0v = s->bs[8 * ab + c0];
                float b1v = s->bs[8 * ab + c0 + 1];
                d[mb][ab][0] = b0v; d[mb][ab][1] = b1v;
                d[mb][ab][2] = b0v; d[mb][ab][3] = b1v;
            }
            d[mb][8][0] = 0.f; d[mb][8][1] = 0.f;
            d[mb][8][2] = 0.f; d[mb][8][3] = 0.f;
        }

        #pragma unroll
        for (int eb = 0; eb < 4; eb++) {
            const int e = 16 * eb + c0;
            // --- build A fragments for this eblk: 2 m-blocks, hi + lo ---
            uint32_t ah[2][4], al[2][4];
            #pragma unroll
            for (int mb = 0; mb < 2; mb++) {
                #pragma unroll
                for (int rr = 0; rr < 2; rr++) {
                    const float* pxi = s->xs + ofsI[mb * 2 + rr];
                    const float* pxj = s->xs + ofsJ[mb * 2 + rr];
                    float2 xa  = *(const float2*)(pxi + e);
                    float2 xb2 = *(const float2*)(pxj + e);
                    float pA0 = xa.x * xb2.x, pA1 = xa.y * xb2.y;
                    float2 xc = *(const float2*)(pxi + e + 8);
                    float2 xd = *(const float2*)(pxj + e + 8);
                    float pB0 = xc.x * xd.x, pB1 = xc.y * xd.y;
                    __half2 hA = __floats2half2_rn(pA0, pA1);
                    __half2 hB = __floats2half2_rn(pB0, pB1);
                    float2 fA = __half22float2(hA);
                    float2 fB = __half22float2(hB);
                    __half2 lA = __floats2half2_rn(pA0 - fA.x, pA1 - fA.y);
                    __half2 lB = __floats2half2_rn(pB0 - fB.x, pB1 - fB.y);
                    ah[mb][rr]     = h2u(hA);
                    ah[mb][rr + 2] = h2u(hB);
                    al[mb][rr]     = h2u(lA);
                    al[mb][rr + 2] = h2u(lB);
                }
            }

            // --- hi-B pass: each fragment feeds 4 MMAs (2 mb x {ah, al}) ---
            #pragma unroll
            for (int ab = 0; ab < NB; ab++) {
                uint2 bfh = s->Whf[(eb * NB + ab) * 32 + lane];
                mma_fp16(d[0][ab], ah[0][0], ah[0][1], ah[0][2], ah[0][3],
                         bfh.x, bfh.y);
                mma_fp16(d[1][ab], ah[1][0], ah[1][1], ah[1][2], ah[1][3],
                         bfh.x, bfh.y);
                mma_fp16(d[0][ab], al[0][0], al[0][1], al[0][2], al[0][3],
                         bfh.x, bfh.y);
                mma_fp16(d[1][ab], al[1][0], al[1][1], al[1][2], al[1][3],
                         bfh.x, bfh.y);
            }
            // --- lo-B pass: 2 MMAs per fragment ---
            #pragma unroll
            for (int ab = 0; ab < NB; ab++) {
                uint2 bfl = s->Wlf[(eb * NB + ab) * 32 + lane];
                mma_fp16(d[0][ab], ah[0][0], ah[0][1], ah[0][2], ah[0][3],
                         bfl.x, bfl.y);
                mma_fp16(d[1][ab], ah[1][0], ah[1][1], ah[1][2], ah[1][3],
                         bfl.x, bfl.y);
            }
        }

        // --- epilogue: relu(z)·h reduce, plus direct q extraction ---
        #pragma unroll
        for (int mb = 0; mb < 2; mb++) {
            float s0 = 0.f, s1 = 0.f;
            #pragma unroll
            for (int ab = 0; ab < 8; ab++) {
                int a = 8 * ab + c0;
                float h0v = s->hs[a], h1v = s->hs[a + 1];
                s0 = fmaf(fmaxf(d[mb][ab][0], 0.f), h0v, s0);
                s0 = fmaf(fmaxf(d[mb][ab][1], 0.f), h1v, s0);
                s1 = fmaf(fmaxf(d[mb][ab][2], 0.f), h0v, s1);
                s1 = fmaf(fmaxf(d[mb][ab][3], 0.f), h1v, s1);
            }
            s0 += __shfl_xor_sync(0xffffffffu, s0, 1);
            s0 += __shfl_xor_sync(0xffffffffu, s0, 2);
            s1 += __shfl_xor_sync(0xffffffffu, s1, 1);
            s1 += __shfl_xor_sync(0xffffffffu, s1, 2);
            if ((lane & 3) == 0) {
                int p0 = prow[mb * 2];
                int p1 = prow[mb * 2 + 1];
                if (p0 < NPAIR) {
                    s->sc[p0] = s0;
                    s->sq[p0] = d[mb][8][0];   // q_p: col 64 lives in lanes c0==0
                }
                if (p1 < NPAIR) {
                    s->sc[p1] = s1;
                    s->sq[p1] = d[mb][8][2];
                }
            }
        }
    }
    __syncthreads();

    // ---------------- Phase 2: fused softmax + weighted dot -------------
    float m = -3.402823466e38f;
    for (int p = tid; p < NPAIR; p += NT) m = fmaxf(m, s->sc[p]);
    #pragma unroll
    for (int o = 16; o; o >>= 1) m = fmaxf(m, __shfl_xor_sync(0xffffffffu, m, o));
    if (lane == 0) s->redm[wid] = m;
    __syncthreads();
    if (tid == 0) {
        float mm = s->redm[0];
        #pragma unroll
        for (int w = 1; w < 8; w++) mm = fmaxf(mm, s->redm[w]);
        s->redm[0] = mm;
    }
    __syncthreads();
    m = s->redm[0];

    float sum = 0.f, dot = 0.f;
    for (int p = tid; p < NPAIR; p += NT) {
        float e0 = __expf(s->sc[p] - m);
        sum += e0;
        dot = fmaf(e0, s->sq[p], dot);
    }
    #pragma unroll
    for (int o = 16; o; o >>= 1) {
        sum += __shfl_xor_sync(0xffffffffu, sum, o);
        dot += __shfl_xor_sync(0xffffffffu, dot, o);
    }
    if (lane == 0) { s->reds[wid] = sum; s->redd[wid] = dot; }
    __syncthreads();
    if (tid == 0) {
        float ss = s->reds[0], dd = s->redd[0];
        #pragma unroll
        for (int w = 1; w < 8; w++) { ss += s->reds[w]; dd += s->redd[w]; }
        out[b] = (float)NPAIR * dd / ss;
    }
}

extern "C" void kernel_launch(void* const* d_in, const int* in_sizes, int n_in,
                              void* d_out, int out_size) {
    const float* x    = (const float*)d_in[0];
    const float* W    = (const float*)d_in[1];
    const float* bias = (const float*)d_in[2];
    const float* h    = (const float*)d_in[3];
    const float* pw   = (const float*)d_in[4];
    float* out = (float*)d_out;

    int B = in_sizes[0] / (FEAT * EDIM);
    size_t smem_bytes = sizeof(Smem);

    static bool attr_set = false;
    if (!attr_set) {
        cudaFuncSetAttribute(afm_main_kernel,
                             cudaFuncAttributeMaxDynamicSharedMemorySize,
                             (int)smem_bytes);
        attr_set = true;
    }

    afm_main_kernel<<<B, NT, smem_bytes>>>(x, W, bias, h, pw, out);
}

// round 10
// speedup vs baseline: 6.9473x; 1.2570x over previous
#include <cuda_runtime.h>
#include <cuda_fp16.h>
#include <cstdint>
#include <cstring>

#define FEAT   40
#define EDIM   64
#define ADIM   64
#define NB     9            // n-blocks: 8 for W (64 cols) + 1 for pw column
#define NPAIR  780          // FEAT*(FEAT-1)/2
#define NT     256
#define SUPER_P 256         // pairs per supertile (8 warps x 32)
#define NSUPER  4           // ceil(780/256)
#define XS_STRIDE 68        // padded x row

// ---------------------------------------------------------------------------
// m16n8k16 fp16 MMA with f32 accumulation (arch-generic, works on sm_100)
// ---------------------------------------------------------------------------
__device__ __forceinline__ void mma_fp16(float d[4],
                                         uint32_t a0, uint32_t a1,
                                         uint32_t a2, uint32_t a3,
                                         uint32_t b0, uint32_t b1) {
    asm volatile(
        "mma.sync.aligned.m16n8k16.row.col.f32.f16.f16.f32 "
        "{%0,%1,%2,%3}, {%4,%5,%6,%7}, {%8,%9}, {%0,%1,%2,%3};"
        : "+f"(d[0]), "+f"(d[1]), "+f"(d[2]), "+f"(d[3])
        : "r"(a0), "r"(a1), "r"(a2), "r"(a3), "r"(b0), "r"(b1));
}

__device__ __forceinline__ uint32_t h2u(__half2 h) {
    uint32_t u;
    memcpy(&u, &h, 4);
    return u;
}

// Precomputed W' fragments (built once by prep_kernel)
__device__ uint2 g_Whf[4 * NB * 32];

__global__ void prep_kernel(const float* __restrict__ W,
                            const float* __restrict__ pw) {
    // B fragments for m16n8k16, W' = [W | pw | 0...]:
    //   n = 8*nblk + lane/4 ; k0 = 16*eblk + (lane%4)*2
    for (int idx = threadIdx.x; idx < 4 * NB * 32; idx += 288) {
        int l    = idx & 31;
        int nblk = (idx >> 5) % NB;
        int eblk = (idx >> 5) / NB;
        int n  = 8 * nblk + (l >> 2);
        int k0 = 16 * eblk + (l & 3) * 2;
        float w00, w01, w10, w11;
        if (n < ADIM) {
            w00 = W[(k0    ) * ADIM + n];
            w01 = W[(k0 + 1) * ADIM + n];
            w10 = W[(k0 + 8) * ADIM + n];
            w11 = W[(k0 + 9) * ADIM + n];
        } else if (n == ADIM) {           // the pw column
            w00 = pw[k0];     w01 = pw[k0 + 1];
            w10 = pw[k0 + 8]; w11 = pw[k0 + 9];
        } else {                           // zero padding cols 65..71
            w00 = w01 = w10 = w11 = 0.f;
        }
        __half2 h0 = __floats2half2_rn(w00, w01);
        __half2 h1 = __floats2half2_rn(w10, w11);
        g_Whf[idx] = make_uint2(h2u(h0), h2u(h1));
    }
}

struct __align__(16) Smem {
    float xs[FEAT * XS_STRIDE];   // 10880
    uint2 Whf[4 * NB * 32];       // 9216  W'-hi fragments [eblk][nblk][lane]
    float sc[NPAIR];              // 3120  scores
    float sq[NPAIR];              // 3120  q_p = BI_p . pw
    float bs[ADIM];
    float hs[ADIM];
    float redm[8];
    float reds[8];
    float redd[8];
    unsigned char pii[NPAIR];
    unsigned char pjj[NPAIR];
};

__global__ __launch_bounds__(NT, 2)
void afm_main_kernel(const float* __restrict__ x,
                     const float* __restrict__ bias,
                     const float* __restrict__ h,
                     float* __restrict__ out) {
    extern __shared__ char smem_raw[];
    Smem* s = reinterpret_cast<Smem*>(smem_raw);

    const int b    = blockIdx.x;
    const int tid  = threadIdx.x;
    const int wid  = tid >> 5;
    const int lane = tid & 31;

    // ---------------- Phase 0: stage inputs (no conversion math) --------
    {
        const float* xb = x + (long)b * FEAT * EDIM;
        for (int idx = tid; idx < FEAT * EDIM; idx += NT) {
            int row = idx >> 6, col = idx & 63;
            s->xs[row * XS_STRIDE + col] = xb[idx];
        }
        // coalesced copy of precomputed fragments: 9216 B = 576 uint4
        const uint4* src = (const uint4*)g_Whf;
        uint4* dst = (uint4*)s->Whf;
        for (int i = tid; i < 576; i += NT) dst[i] = src[i];
        if (tid < ADIM) { s->bs[tid] = bias[tid]; s->hs[tid] = h[tid]; }
        if (tid < FEAT - 1) {
            int i = tid;
            int base = i * (FEAT - 1) - i * (i - 1) / 2;
            for (int j = i + 1; j < FEAT; j++) {
                s->pii[base + j - i - 1] = (unsigned char)i;
                s->pjj[base + j - i - 1] = (unsigned char)j;
            }
        }
    }
    __syncthreads();

    const int r  = lane >> 2;        // row-within-16 (0..7)
    const int c0 = (lane & 3) * 2;   // col pair base

    // ---------------- Phase 1: warp-independent fp16-split MMA ----------
    // A split hi+lo (22-bit), W single fp16 (11-bit) -> 4 MMAs per fragment.
    for (int st = 0; st < NSUPER; st++) {
        const int pbase = st * SUPER_P + wid * 32;
        if (pbase >= NPAIR) continue;

        int prow[4];                  // [mb*2 + (0:r,1:r+8)]
        int ofsI[4], ofsJ[4];
        #pragma unroll
        for (int q = 0; q < 4; q++) {
            int p = pbase + 16 * (q >> 1) + r + 8 * (q & 1);
            prow[q] = p;
            int ii = (p < NPAIR) ? s->pii[p] : 0;
            int jj = (p < NPAIR) ? s->pjj[p] : 0;
            ofsI[q] = ii * XS_STRIDE;
            ofsJ[q] = jj * XS_STRIDE;
        }

        // D accumulators: d[mb][nb][4]; bias for nb<8, zero for the q column
        float d[2][NB][4];
        #pragma unroll
        for (int mb = 0; mb < 2; mb++) {
            #pragma unroll
            for (int ab = 0; ab < 8; ab++) {
                float b0v = s->bs[8 * ab + c0];
                float b1v = s->bs[8 * ab + c0 + 1];
                d[mb][ab][0] = b0v; d[mb][ab][1] = b1v;
                d[mb][ab][2] = b0v; d[mb][ab][3] = b1v;
            }
            d[mb][8][0] = 0.f; d[mb][8][1] = 0.f;
            d[mb][8][2] = 0.f; d[mb][8][3] = 0.f;
        }

        #pragma unroll
        for (int eb = 0; eb < 4; eb++) {
            const int e = 16 * eb + c0;
            // --- build A fragments for this eblk: 2 m-blocks, hi + lo ---
            uint32_t ah[2][4], al[2][4];
            #pragma unroll
            for (int mb = 0; mb < 2; mb++) {
                #pragma unroll
                for (int rr = 0; rr < 2; rr++) {
                    const float* pxi = s->xs + ofsI[mb * 2 + rr];
                    const float* pxj = s->xs + ofsJ[mb * 2 + rr];
                    float2 xa  = *(const float2*)(pxi + e);
                    float2 xb2 = *(const float2*)(pxj + e);
                    float pA0 = xa.x * xb2.x, pA1 = xa.y * xb2.y;
                    float2 xc = *(const float2*)(pxi + e + 8);
                    float2 xd = *(const float2*)(pxj + e + 8);
                    float pB0 = xc.x * xd.x, pB1 = xc.y * xd.y;
                    __half2 hA = __floats2half2_rn(pA0, pA1);
                    __half2 hB = __floats2half2_rn(pB0, pB1);
                    float2 fA = __half22float2(hA);
                    float2 fB = __half22float2(hB);
                    __half2 lA = __floats2half2_rn(pA0 - fA.x, pA1 - fA.y);
                    __half2 lB = __floats2half2_rn(pB0 - fB.x, pB1 - fB.y);
                    ah[mb][rr]     = h2u(hA);
                    ah[mb][rr + 2] = h2u(hB);
                    al[mb][rr]     = h2u(lA);
                    al[mb][rr + 2] = h2u(lB);
                }
            }

            // --- each fragment feeds 4 MMAs (2 mb x {ah, al}) ---
            #pragma unroll
            for (int ab = 0; ab < NB; ab++) {
                uint2 bfh = s->Whf[(eb * NB + ab) * 32 + lane];
                mma_fp16(d[0][ab], ah[0][0], ah[0][1], ah[0][2], ah[0][3],
                         bfh.x, bfh.y);
                mma_fp16(d[1][ab], ah[1][0], ah[1][1], ah[1][2], ah[1][3],
                         bfh.x, bfh.y);
                mma_fp16(d[0][ab], al[0][0], al[0][1], al[0][2], al[0][3],
                         bfh.x, bfh.y);
                mma_fp16(d[1][ab], al[1][0], al[1][1], al[1][2], al[1][3],
                         bfh.x, bfh.y);
            }
        }

        // --- epilogue: relu(z)·h reduce, plus direct q extraction ---
        #pragma unroll
        for (int mb = 0; mb < 2; mb++) {
            float s0 = 0.f, s1 = 0.f;
            #pragma unroll
            for (int ab = 0; ab < 8; ab++) {
                int a = 8 * ab + c0;
                float h0v = s->hs[a], h1v = s->hs[a + 1];
                s0 = fmaf(fmaxf(d[mb][ab][0], 0.f), h0v, s0);
                s0 = fmaf(fmaxf(d[mb][ab][1], 0.f), h1v, s0);
                s1 = fmaf(fmaxf(d[mb][ab][2], 0.f), h0v, s1);
                s1 = fmaf(fmaxf(d[mb][ab][3], 0.f), h1v, s1);
            }
            s0 += __shfl_xor_sync(0xffffffffu, s0, 1);
            s0 += __shfl_xor_sync(0xffffffffu, s0, 2);
            s1 += __shfl_xor_sync(0xffffffffu, s1, 1);
            s1 += __shfl_xor_sync(0xffffffffu, s1, 2);
            if ((lane & 3) == 0) {
                int p0 = prow[mb * 2];
                int p1 = prow[mb * 2 + 1];
                if (p0 < NPAIR) {
                    s->sc[p0] = s0;
                    s->sq[p0] = d[mb][8][0];   // q_p: col 64 lives in lanes c0==0
                }
                if (p1 < NPAIR) {
                    s->sc[p1] = s1;
                    s->sq[p1] = d[mb][8][2];
                }
            }
        }
    }
    __syncthreads();

    // ---------------- Phase 2: fused softmax + weighted dot -------------
    float m = -3.402823466e38f;
    for (int p = tid; p < NPAIR; p += NT) m = fmaxf(m, s->sc[p]);
    #pragma unroll
    for (int o = 16; o; o >>= 1) m = fmaxf(m, __shfl_xor_sync(0xffffffffu, m, o));
    if (lane == 0) s->redm[wid] = m;
    __syncthreads();
    if (tid == 0) {
        float mm = s->redm[0];
        #pragma unroll
        for (int w = 1; w < 8; w++) mm = fmaxf(mm, s->redm[w]);
        s->redm[0] = mm;
    }
    __syncthreads();
    m = s->redm[0];

    float sum = 0.f, dot = 0.f;
    for (int p = tid; p < NPAIR; p += NT) {
        float e0 = __expf(s->sc[p] - m);
        sum += e0;
        dot = fmaf(e0, s->sq[p], dot);
    }
    #pragma unroll
    for (int o = 16; o; o >>= 1) {
        sum += __shfl_xor_sync(0xffffffffu, sum, o);
        dot += __shfl_xor_sync(0xffffffffu, dot, o);
    }
    if (lane == 0) { s->reds[wid] = sum; s->redd[wid] = dot; }
    __syncthreads();
    if (tid == 0) {
        float ss = s->reds[0], dd = s->redd[0];
        #pragma unroll
        for (int w = 1; w < 8; w++) { ss += s->reds[w]; dd += s->redd[w]; }
        out[b] = (float)NPAIR * dd / ss;
    }
}

extern "C" void kernel_launch(void* const* d_in, const int* in_sizes, int n_in,
                              void* d_out, int out_size) {
    const float* x    = (const float*)d_in[0];
    const float* W    = (const float*)d_in[1];
    const float* bias = (const float*)d_in[2];
    const float* h    = (const float*)d_in[3];
    const float* pw   = (const float*)d_in[4];
    float* out = (float*)d_out;

    int B = in_sizes[0] / (FEAT * EDIM);
    size_t smem_bytes = sizeof(Smem);

    static bool attr_set = false;
    if (!attr_set) {
        cudaFuncSetAttribute(afm_main_kernel,
                             cudaFuncAttributeMaxDynamicSharedMemorySize,
                             (int)smem_bytes);
        attr_set = true;
    }

    prep_kernel<<<1, 288>>>(W, pw);
    afm_main_kernel<<<B, NT, smem_bytes>>>(x, bias, h, out);
}